// round 4
// baseline (speedup 1.0000x reference)
#include <cuda_runtime.h>
#include <cuda_bf16.h>
#include <cstdint>

#define N_NODES   50000
#define N_EDGES   800000
#define N_FEAT    128
#define HIDDEN    64
#define N_GRAPHS  256
#define NB_SCAN   196               // 196*256 = 50176 >= N_NODES

// ---------------- scratch ----------------------------------------------------
__device__ __align__(16) int    d_src[N_EDGES];
__device__ __align__(16) int    d_dst[N_EDGES];
__device__ __align__(16) int    d_csr_src[N_EDGES];
__device__ int    d_batch[N_NODES];
__device__ int    d_flag;                 // 1 => int64 inputs, 0 => int32
__device__ int    d_ecnt[N_NODES];
__device__ int    d_ptr[N_NODES];
__device__ int    d_cur[N_NODES];
__device__ int    d_bagg[NB_SCAN];        // lookback: block aggregate
__device__ int    d_binc[NB_SCAN];        // lookback: inclusive prefix
__device__ int    d_bflag[NB_SCAN];       // 0=none 1=agg 2=inclusive
__device__ float  d_dis[N_NODES];
__device__ __align__(16) float4 d_ga[(N_NODES + 1) * 16];  // layer-1 g (+zero row)
__device__ __align__(16) float4 d_gb[(N_NODES + 1) * 16];  // layer-2 g (+zero row)
__device__ float  d_pool[N_GRAPHS * HIDDEN];
__device__ float  d_cnt[N_GRAPHS];

// ---------------- prep: zero scratch + dtype flag ------------------------------
__global__ void k_prep(const int* __restrict__ ebuf) {
    int i = blockIdx.x * blockDim.x + threadIdx.x;
    if (i < N_NODES) d_ecnt[i] = 0;
    if (i < N_GRAPHS * HIDDEN) d_pool[i] = 0.f;
    if (i < N_GRAPHS) d_cnt[i] = 0.f;
    if (i < NB_SCAN) d_bflag[i] = 0;
    if (i < 16) {
        d_ga[N_NODES * 16 + i] = make_float4(0.f, 0.f, 0.f, 0.f);
        d_gb[N_NODES * 16 + i] = make_float4(0.f, 0.f, 0.f, 0.f);
    }
    if (blockIdx.x == 0) {
        __shared__ int ok;
        if (threadIdx.x == 0) ok = 1;
        __syncthreads();
        int bad = 0;
        for (int t = threadIdx.x; t < 1024; t += blockDim.x)
            if (ebuf[2 * t + 1] != 0) bad = 1;
        if (bad) ok = 0;
        __syncthreads();
        if (threadIdx.x == 0) d_flag = ok;
    }
}

// ---------------- convert (4 edges/thread) + histogram + batch -----------------
__global__ void k_convert(const void* __restrict__ e, const void* __restrict__ b) {
    int t = blockIdx.x * blockDim.x + threadIdx.x;
    int f = d_flag;
    int e0 = t * 4;
    if (e0 < N_EDGES) {
        int s[4], dd[4];
        if (f) {
            const long long* p = (const long long*)e;
#pragma unroll
            for (int k = 0; k < 4; k++) { s[k] = (int)p[e0 + k]; dd[k] = (int)p[e0 + k + N_EDGES]; }
        } else {
            const int* p = (const int*)e;
#pragma unroll
            for (int k = 0; k < 4; k++) { s[k] = p[e0 + k]; dd[k] = p[e0 + k + N_EDGES]; }
        }
        ((int4*)d_src)[t] = make_int4(s[0], s[1], s[2], s[3]);
        ((int4*)d_dst)[t] = make_int4(dd[0], dd[1], dd[2], dd[3]);
#pragma unroll
        for (int k = 0; k < 4; k++) atomicAdd(&d_ecnt[dd[k]], 1);
    }
    if (t < N_NODES) {
        int bb = f ? (int)((const long long*)b)[t] : ((const int*)b)[t];
        d_batch[t] = bb;
        atomicAdd(&d_cnt[bb], 1.0f);
    }
}

// ---------------- single-pass scan (decoupled lookback) ------------------------
__global__ void __launch_bounds__(256) k_scan() {
    __shared__ int sm[256];
    __shared__ int s_exc;
    int t = threadIdx.x, bid = blockIdx.x;
    int i = bid * 256 + t;
    int v = (i < N_NODES) ? d_ecnt[i] : 0;
    sm[t] = v;
    __syncthreads();
    for (int off = 1; off < 256; off <<= 1) {
        int u = (t >= off) ? sm[t - off] : 0;
        __syncthreads();
        sm[t] += u;
        __syncthreads();
    }
    int incl = sm[t];                        // inclusive within block
    int total = sm[255];
    if (t == 0) {
        d_bagg[bid] = total;
        __threadfence();
        d_bflag[bid] = 1;
    }
    if (t < 32) {                            // warp-0 lookback
        int sum = 0;
        int pos = bid - 1;
        while (pos >= 0) {
            int p = pos - t;
            int fl = 0, val = 0;
            if (p >= 0) {
                do { fl = ((volatile int*)d_bflag)[p]; } while (fl == 0);
                val = (fl == 2) ? ((volatile int*)d_binc)[p]
                                : ((volatile int*)d_bagg)[p];
            }
            unsigned ball = __ballot_sync(0xffffffffu, fl == 2 && p >= 0);
            if (ball) {
                int lead = __ffs(ball) - 1;  // smallest t => largest p with inclusive
                sum += (t <= lead) ? val : 0;
                pos = -1;
            } else {
                sum += (p >= 0) ? val : 0;
                pos -= 32;
            }
        }
        for (int o = 16; o; o >>= 1) sum += __shfl_down_sync(0xffffffffu, sum, o);
        if (t == 0) {
            s_exc = sum;
            d_binc[bid] = sum + total;
            __threadfence();
            d_bflag[bid] = 2;
        }
    }
    __syncthreads();
    if (i < N_NODES) {
        int p = s_exc + incl - v;
        d_ptr[i] = p;
        d_cur[i] = p;
        d_dis[i] = rsqrtf((float)(v + 1));
    }
}

// ---------------- CSR fill -----------------------------------------------------
__global__ void k_fill() {
    int t = blockIdx.x * blockDim.x + threadIdx.x;
    int e0 = t * 4;
    if (e0 >= N_EDGES) return;
    int4 s4 = ((const int4*)d_src)[t];
    int4 d4 = ((const int4*)d_dst)[t];
    int p0 = atomicAdd(&d_cur[d4.x], 1);
    int p1 = atomicAdd(&d_cur[d4.y], 1);
    int p2 = atomicAdd(&d_cur[d4.z], 1);
    int p3 = atomicAdd(&d_cur[d4.w], 1);
    d_csr_src[p0] = s4.x;
    d_csr_src[p1] = s4.y;
    d_csr_src[p2] = s4.z;
    d_csr_src[p3] = s4.w;
}

// ---------------- GEMM1: Ga = dis * (X @ W1) -----------------------------------
__global__ void __launch_bounds__(256) k_gemm1(const float* __restrict__ X,
                                               const float* __restrict__ W) {
    __shared__ float4 sw[N_FEAT * 16];       // 32 KB
    __shared__ float  sx[64][N_FEAT];        // 32 KB
    int tid = threadIdx.x;
    int w = tid >> 5, lane = tid & 31, h = lane >> 4, l16 = lane & 15;
    for (int i = tid; i < N_FEAT * 16; i += 256) sw[i] = ((const float4*)W)[i];
    int row0 = blockIdx.x * 64;
    const float4* X4 = (const float4*)X;
    for (int i = tid; i < 64 * 32; i += 256) {
        int r = i >> 5, c = i & 31;
        int row = row0 + r;
        float4 v = (row < N_NODES) ? X4[row * 32 + c] : make_float4(0.f, 0.f, 0.f, 0.f);
        ((float4*)&sx[r][0])[c] = v;
    }
    __syncthreads();
    int rbase = w * 8 + h * 4;
    float4 acc[4] = {{0,0,0,0},{0,0,0,0},{0,0,0,0},{0,0,0,0}};
    for (int k = 0; k < N_FEAT; k += 4) {
        float4 w0 = sw[(k + 0) * 16 + l16];
        float4 w1 = sw[(k + 1) * 16 + l16];
        float4 w2 = sw[(k + 2) * 16 + l16];
        float4 w3 = sw[(k + 3) * 16 + l16];
#pragma unroll
        for (int r = 0; r < 4; r++) {
            float4 xv = *(const float4*)&sx[rbase + r][k];
            acc[r].x += xv.x * w0.x + xv.y * w1.x + xv.z * w2.x + xv.w * w3.x;
            acc[r].y += xv.x * w0.y + xv.y * w1.y + xv.z * w2.y + xv.w * w3.y;
            acc[r].z += xv.x * w0.z + xv.y * w1.z + xv.z * w2.z + xv.w * w3.z;
            acc[r].w += xv.x * w0.w + xv.y * w1.w + xv.z * w2.w + xv.w * w3.w;
        }
    }
#pragma unroll
    for (int r = 0; r < 4; r++) {
        int row = row0 + rbase + r;
        if (row < N_NODES) {
            float s = d_dis[row];
            float4 v = acc[r];
            d_ga[row * 16 + l16] = make_float4(v.x*s, v.y*s, v.z*s, v.w*s);
        }
    }
}

// ---------------- CSR gather: half-warp float4, 2 edges in flight --------------
__device__ __forceinline__ float4 agg_node4(const float4* __restrict__ g4,
                                            int node, int h, int l16, int lane) {
    int start = d_ptr[node];
    int n = d_ecnt[node];
    float4 accA = make_float4(0.f, 0.f, 0.f, 0.f);
    float4 accB = make_float4(0.f, 0.f, 0.f, 0.f);
    if (h == 0) accA = g4[node * 16 + l16];            // self-loop once
    for (int base = 0; base < n; base += 32) {
        int rem = n - base;
        int idx = (lane < rem) ? d_csr_src[start + base + lane] : N_NODES;
        int mm = (rem < 32) ? ((rem + 7) & ~7) : 32;   // pad to 8; zero row covers tail
#pragma unroll 1
        for (int jj = 0; jj < mm; jj += 8) {
#pragma unroll
            for (int j = 0; j < 8; j += 2) {
                int s = __shfl_sync(0xffffffffu, idx, jj + j + h);
                float4 a = g4[s * 16 + l16];
                if (j & 2) { accB.x += a.x; accB.y += a.y; accB.z += a.z; accB.w += a.w; }
                else       { accA.x += a.x; accA.y += a.y; accA.z += a.z; accA.w += a.w; }
            }
        }
    }
    float4 acc = make_float4(accA.x + accB.x, accA.y + accB.y,
                             accA.z + accB.z, accA.w + accB.w);
    acc.x += __shfl_xor_sync(0xffffffffu, acc.x, 16);
    acc.y += __shfl_xor_sync(0xffffffffu, acc.y, 16);
    acc.z += __shfl_xor_sync(0xffffffffu, acc.z, 16);
    acc.w += __shfl_xor_sync(0xffffffffu, acc.w, 16);
    return acc;                                         // valid on all lanes
}

// ---------------- agg1 + fused GEMM2 -------------------------------------------
__global__ void __launch_bounds__(256) k_agg1(const float* __restrict__ bias,
                                              const float* __restrict__ W2) {
    __shared__ float2 sw2[HIDDEN * 32];      // 16 KB
    __shared__ float  sh[8][HIDDEN];         // 2 KB
    int tid = threadIdx.x;
    for (int i = tid; i < HIDDEN * 32; i += 256) sw2[i] = ((const float2*)W2)[i];
    __syncthreads();
    int w = tid >> 5, lane = tid & 31, h = lane >> 4, l16 = lane & 15;
    int node = blockIdx.x * 8 + w;
    float4 acc = agg_node4(d_ga, node, h, l16, lane);
    float s = d_dis[node];
    if (h == 0) {
        float4 bb = ((const float4*)bias)[l16];
        float4 r;
        r.x = fmaxf(s * acc.x + bb.x, 0.f);
        r.y = fmaxf(s * acc.y + bb.y, 0.f);
        r.z = fmaxf(s * acc.z + bb.z, 0.f);
        r.w = fmaxf(s * acc.w + bb.w, 0.f);
        ((float4*)&sh[w][0])[l16] = r;
    }
    __syncwarp();
    float2 o = make_float2(0.f, 0.f);
#pragma unroll
    for (int k = 0; k < HIDDEN; k++) {
        float hk = sh[w][k];
        float2 wv = sw2[k * 32 + lane];
        o.x += hk * wv.x;
        o.y += hk * wv.y;
    }
    ((float2*)d_gb)[node * 32 + lane] = make_float2(o.x * s, o.y * s);
}

// ---------------- agg2 + pooled RED --------------------------------------------
__global__ void __launch_bounds__(256) k_agg2(const float* __restrict__ bias) {
    int tid = threadIdx.x;
    int w = tid >> 5, lane = tid & 31, h = lane >> 4, l16 = lane & 15;
    int node = blockIdx.x * 8 + w;
    float4 acc = agg_node4(d_gb, node, h, l16, lane);
    if (h == 0) {
        float s = d_dis[node];
        float4 bb = ((const float4*)bias)[l16];
        float rx = fmaxf(s * acc.x + bb.x, 0.f);
        float ry = fmaxf(s * acc.y + bb.y, 0.f);
        float rz = fmaxf(s * acc.z + bb.z, 0.f);
        float rw = fmaxf(s * acc.w + bb.w, 0.f);
        int b = d_batch[node];
        float* p = &d_pool[b * HIDDEN + l16 * 4];
        asm volatile("red.global.add.v4.f32 [%0], {%1, %2, %3, %4};"
                     :: "l"(p), "f"(rx), "f"(ry), "f"(rz), "f"(rw) : "memory");
    }
}

// ---------------- MLP head ------------------------------------------------------
__global__ void k_mlp(const float* __restrict__ Wm1, const float* __restrict__ bm1,
                      const float* __restrict__ Wm2, const float* __restrict__ bm2,
                      float* __restrict__ out) {
    __shared__ float sp[HIDDEN];
    __shared__ float sred[HIDDEN];
    int g = blockIdx.x, j = threadIdx.x;
    float inv = 1.0f / fmaxf(d_cnt[g], 1.0f);
    sp[j] = d_pool[g * HIDDEN + j] * inv;
    __syncthreads();
    float acc = bm1[j];
#pragma unroll
    for (int k = 0; k < HIDDEN; k++) acc += sp[k] * Wm1[k * HIDDEN + j];
    float v = fmaxf(acc, 0.f) * Wm2[j];
    sred[j] = v;
    __syncthreads();
    if (j < 32) {
        float t = sred[j] + sred[j + 32];
        for (int o = 16; o; o >>= 1) t += __shfl_down_sync(0xffffffff, t, o);
        if (j == 0) out[g] = t + bm2[0];
    }
}

// ---------------- launch --------------------------------------------------------
extern "C" void kernel_launch(void* const* d_in, const int* in_sizes, int n_in,
                              void* d_out, int out_size) {
    const float* x   = (const float*)d_in[0];
    const void*  ei  = d_in[1];
    const void*  bt  = d_in[2];
    const float* W1  = (const float*)d_in[3];
    const float* b1  = (const float*)d_in[4];
    const float* W2  = (const float*)d_in[5];
    const float* b2  = (const float*)d_in[6];
    const float* Wm1 = (const float*)d_in[7];
    const float* bm1 = (const float*)d_in[8];
    const float* Wm2 = (const float*)d_in[9];
    const float* bm2 = (const float*)d_in[10];
    float* out = (float*)d_out;

    k_prep<<<200, 256>>>((const int*)ei);
    k_convert<<<(N_EDGES / 4 + 255) / 256, 256>>>(ei, bt);
    k_scan<<<NB_SCAN, 256>>>();
    k_fill<<<(N_EDGES / 4 + 255) / 256, 256>>>();

    k_gemm1<<<(N_NODES + 63) / 64, 256>>>(x, W1);
    k_agg1<<<N_NODES / 8, 256>>>(b1, W2);
    k_agg2<<<N_NODES / 8, 256>>>(b2);

    k_mlp<<<N_GRAPHS, HIDDEN>>>(Wm1, bm1, Wm2, bm2, out);
}